// round 12
// baseline (speedup 1.0000x reference)
#include <cuda_runtime.h>

#define N_NODES 50000
#define N_EDGES 800000
#define D 128
#define NBATCH 64

// ---------------- device scratch (allocation-free) ----------------
// g_agg / g_S / g_cnt are self-restoring (zero before & after each launch).
__device__ float g_agg[N_NODES * D];      // neighbor sums (re-zeroed by epilogue)
__device__ float g_S[NBATCH * D];         // pooled sums (re-zeroed by k_pool)
__device__ float g_cnt[NBATCH];           // batch counts (re-zeroed by k_pool)
__device__ int   g_deg[N_NODES];          // per-src degree (zeroed by k_setup)
__device__ int   g_rowstart[N_NODES + 1]; // CSR-by-src offsets
__device__ int   g_cursor[N_NODES];       // fill cursors
__device__ int   g_csr[N_EDGES];          // dst indices grouped by src

// ---------------------------------------------------------------------------
// 0) zero per-src degree
// ---------------------------------------------------------------------------
__global__ void k_setup() {
    int i = blockIdx.x * blockDim.x + threadIdx.x;
    if (i < N_NODES) g_deg[i] = 0;
}

// ---------------------------------------------------------------------------
// 1) histogram of src
// ---------------------------------------------------------------------------
__global__ void k_hist(const int* __restrict__ ei) {
    int e = blockIdx.x * blockDim.x + threadIdx.x;
    if (e < N_EDGES) atomicAdd(&g_deg[__ldg(&ei[e])], 1);
}

// ---------------------------------------------------------------------------
// 2) exclusive scan of g_deg -> g_rowstart (+ cursor copy). One 1024-thr block.
// ---------------------------------------------------------------------------
__global__ void k_scan() {
    __shared__ int sums[1024];
    const int CH = (N_NODES + 1023) / 1024;   // 49
    int t = threadIdx.x;
    int beg = t * CH;
    int end = beg + CH; if (end > N_NODES) end = N_NODES;

    int s = 0;
    for (int i = beg; i < end; i++) s += g_deg[i];
    sums[t] = s;
    __syncthreads();
    for (int off = 1; off < 1024; off <<= 1) {
        int v = (t >= off) ? sums[t - off] : 0;
        __syncthreads();
        sums[t] += v;
        __syncthreads();
    }
    int run = (t == 0) ? 0 : sums[t - 1];
    for (int i = beg; i < end; i++) {
        g_rowstart[i] = run;
        g_cursor[i]   = run;
        run += g_deg[i];
    }
    if (t == 0) g_rowstart[N_NODES] = N_EDGES;
}

// ---------------------------------------------------------------------------
// 3) permute: csr[cursor[src]++] = dst.  4 edges per thread -> 4 independent
//    atomic chains (MLP 4) instead of 1.
// ---------------------------------------------------------------------------
__global__ void k_fill(const int* __restrict__ ei) {
    int t = blockIdx.x * blockDim.x + threadIdx.x;
    int e0 = t * 4;
    #pragma unroll
    for (int k = 0; k < 4; k++) {
        int e = e0 + k;
        if (e < N_EDGES) {
            int src = __ldg(&ei[e]);
            int dst = __ldg(&ei[N_EDGES + e]);
            int p = atomicAdd(&g_cursor[src], 1);
            g_csr[p] = dst;
        }
    }
}

// ---------------------------------------------------------------------------
// 4) scatter with src-reuse: one warp per src row. x[src] loaded ONCE into
//    registers, then one fire-and-forget vector RED per out-edge.
//    Edge-loop L2 bytes: 512/edge (RED) + 4/edge (csr) — vs 1024/edge before.
// ---------------------------------------------------------------------------
__global__ void __launch_bounds__(256) k_scatter(const float* __restrict__ x) {
    int row  = (blockIdx.x * blockDim.x + threadIdx.x) >> 5;
    int lane = threadIdx.x & 31;
    if (row >= N_NODES) return;

    const float4* x4 = reinterpret_cast<const float4*>(x);
    float4 v = __ldcg(&x4[(size_t)row * 32 + lane]);   // this src's row chunk

    int s0 = g_rowstart[row];
    int s1 = g_rowstart[row + 1];
    for (int base = s0; base < s1; base += 32) {
        int n = s1 - base; if (n > 32) n = 32;
        int idx = (base + lane < s1) ? g_csr[base + lane] : 0;   // coalesced
        #pragma unroll 4
        for (int j = 0; j < n; j++) {
            int d = __shfl_sync(0xffffffffu, idx, j);
            float* p = g_agg + (size_t)d * D + lane * 4;
            asm volatile("red.global.add.v4.f32 [%0], {%1, %2, %3, %4};"
                         :: "l"(p), "f"(v.x), "f"(v.y), "f"(v.z), "f"(v.w)
                         : "memory");
        }
    }
}

// ---------------------------------------------------------------------------
// 5) epilogue: out = relu(scale*x + agg), re-zero agg, per-batch pooled sums
//    with run-length compression (batch sorted). One warp per 16 rows.
// ---------------------------------------------------------------------------
#define EPI_ROWS 16

__global__ void __launch_bounds__(256) k_epilogue(const float* __restrict__ x,
                                                  const float* __restrict__ eps,
                                                  const int* __restrict__ batch,
                                                  float* __restrict__ out) {
    int warp = (blockIdx.x * blockDim.x + threadIdx.x) >> 5;
    int lane = threadIdx.x & 31;
    int r0 = warp * EPI_ROWS;
    if (r0 >= N_NODES) return;
    int r1 = r0 + EPI_ROWS; if (r1 > N_NODES) r1 = N_NODES;

    float scale = 1.0f + eps[0];
    float4* agg4 = reinterpret_cast<float4*>(g_agg);
    const float4* x4 = reinterpret_cast<const float4*>(x);
    float4* out4 = reinterpret_cast<float4*>(out);
    const float4 zero4 = make_float4(0.f, 0.f, 0.f, 0.f);

    float4 acc = zero4;
    int cnt = 0;
    int cur = batch[r0];

    for (int r = r0; r < r1; r++) {
        size_t idx = (size_t)r * 32 + lane;
        float4 a  = __ldcg(&agg4[idx]);
        float4 xv = x4[idx];
        float4 v;
        v.x = fmaxf(fmaf(xv.x, scale, a.x), 0.f);
        v.y = fmaxf(fmaf(xv.y, scale, a.y), 0.f);
        v.z = fmaxf(fmaf(xv.z, scale, a.z), 0.f);
        v.w = fmaxf(fmaf(xv.w, scale, a.w), 0.f);
        out4[idx] = v;
        agg4[idx] = zero4;                 // self-restore for next replay

        int b = batch[r];
        if (b != cur) {
            float* p = &g_S[cur * D + lane * 4];
            asm volatile("red.global.add.v4.f32 [%0], {%1, %2, %3, %4};"
                         :: "l"(p), "f"(acc.x), "f"(acc.y), "f"(acc.z), "f"(acc.w)
                         : "memory");
            if (lane == 0) atomicAdd(&g_cnt[cur], (float)cnt);
            cur = b; acc = zero4; cnt = 0;
        }
        acc.x += v.x; acc.y += v.y; acc.z += v.z; acc.w += v.w;
        cnt++;
    }
    {
        float* p = &g_S[cur * D + lane * 4];
        asm volatile("red.global.add.v4.f32 [%0], {%1, %2, %3, %4};"
                     :: "l"(p), "f"(acc.x), "f"(acc.y), "f"(acc.z), "f"(acc.w)
                     : "memory");
        if (lane == 0) atomicAdd(&g_cnt[cur], (float)cnt);
    }
}

// ---------------------------------------------------------------------------
// 6) pooled2[b] = S[b] @ W + cnt[b]*bias. Reads then re-zeroes g_S / g_cnt.
// ---------------------------------------------------------------------------
__global__ void k_pool(const float* __restrict__ W,
                       const float* __restrict__ bias,
                       float* __restrict__ out2) {
    int b = blockIdx.x;     // 0..63
    int j = threadIdx.x;    // 0..127
    __shared__ float s[D];
    __shared__ float cntf;
    s[j] = g_S[b * D + j];
    g_S[b * D + j] = 0.0f;                 // self-restore
    if (j == 0) { cntf = g_cnt[b]; g_cnt[b] = 0.0f; }
    __syncthreads();

    float a0 = 0.f, a1 = 0.f, a2 = 0.f, a3 = 0.f;
    #pragma unroll
    for (int k = 0; k < D; k += 4) {
        a0 = fmaf(s[k + 0], __ldg(&W[(k + 0) * D + j]), a0);
        a1 = fmaf(s[k + 1], __ldg(&W[(k + 1) * D + j]), a1);
        a2 = fmaf(s[k + 2], __ldg(&W[(k + 2) * D + j]), a2);
        a3 = fmaf(s[k + 3], __ldg(&W[(k + 3) * D + j]), a3);
    }
    out2[b * D + j] = cntf * bias[j] + ((a0 + a1) + (a2 + a3));
}

// ---------------------------------------------------------------------------
// launch: x, eps, W_pred, b_pred, edge_index, batch -> out | pooled2
// ---------------------------------------------------------------------------
extern "C" void kernel_launch(void* const* d_in, const int* in_sizes, int n_in,
                              void* d_out, int out_size) {
    const float* x     = (const float*)d_in[0];
    const float* eps   = (const float*)d_in[1];
    const float* Wp    = (const float*)d_in[2];
    const float* bp    = (const float*)d_in[3];
    const int*   ei    = (const int*)d_in[4];
    const int*   batch = (const int*)d_in[5];

    float* out  = (float*)d_out;
    float* out2 = out + (size_t)N_NODES * D;

    k_setup<<<(N_NODES + 255) / 256, 256>>>();
    k_hist <<<(N_EDGES + 255) / 256, 256>>>(ei);
    k_scan <<<1, 1024>>>();
    k_fill <<<(N_EDGES / 4 + 255) / 256, 256>>>(ei);

    {
        long long threads = (long long)N_NODES * 32;
        int blocks = (int)((threads + 255) / 256);           // 6250
        k_scatter<<<blocks, 256>>>(x);
    }

    {
        int warps = (N_NODES + EPI_ROWS - 1) / EPI_ROWS;     // 3125
        int blocks = (warps * 32 + 255) / 256;               // 391
        k_epilogue<<<blocks, 256>>>(x, eps, batch, out);
    }

    k_pool<<<NBATCH, 128>>>(Wp, bp, out2);
}

// round 13
// speedup vs baseline: 1.1984x; 1.1984x over previous
#include <cuda_runtime.h>

#define N_NODES 50000
#define N_EDGES 800000
#define D 128
#define NBATCH 64
#define EPW 32                 // edges per warp (800000 = 25000*32), fixed unroll

// ---------------- device scratch (allocation-free) ----------------
__device__ float g_agg[N_NODES * D];      // neighbor sums (re-zeroed by epilogue)
__device__ float g_S[NBATCH * D];         // pooled sums (re-zeroed by k_pool)
__device__ float g_cnt[NBATCH];           // batch counts (re-zeroed by k_pool)
__device__ int   g_deg[N_NODES];          // per-src degree (zeroed by k_setup)
__device__ int   g_cursor[N_NODES];       // fill cursors (set by k_scan)
__device__ int2  g_e2[N_EDGES];           // (src,dst) pairs sorted by src

// ---------------------------------------------------------------------------
// 0) zero per-src degree
// ---------------------------------------------------------------------------
__global__ void k_setup() {
    int i = blockIdx.x * blockDim.x + threadIdx.x;
    if (i < N_NODES) g_deg[i] = 0;
}

// ---------------------------------------------------------------------------
// 1) histogram of src (atomicAdd w/ unused result -> RED)
// ---------------------------------------------------------------------------
__global__ void k_hist(const int* __restrict__ ei) {
    int e = blockIdx.x * blockDim.x + threadIdx.x;
    if (e < N_EDGES) atomicAdd(&g_deg[__ldg(&ei[e])], 1);
}

// ---------------------------------------------------------------------------
// 2) exclusive scan of g_deg -> g_cursor. One 1024-thread block.
// ---------------------------------------------------------------------------
__global__ void k_scan() {
    __shared__ int sums[1024];
    const int CH = (N_NODES + 1023) / 1024;   // 49
    int t = threadIdx.x;
    int beg = t * CH;
    int end = beg + CH; if (end > N_NODES) end = N_NODES;

    int s = 0;
    for (int i = beg; i < end; i++) s += g_deg[i];
    sums[t] = s;
    __syncthreads();
    for (int off = 1; off < 1024; off <<= 1) {
        int v = (t >= off) ? sums[t - off] : 0;
        __syncthreads();
        sums[t] += v;
        __syncthreads();
    }
    int run = (t == 0) ? 0 : sums[t - 1];
    for (int i = beg; i < end; i++) {
        g_cursor[i] = run;
        run += g_deg[i];
    }
}

// ---------------------------------------------------------------------------
// 3) permute into src-sorted (src,dst) pairs
// ---------------------------------------------------------------------------
__global__ void k_fill(const int* __restrict__ ei) {
    int e = blockIdx.x * blockDim.x + threadIdx.x;
    if (e >= N_EDGES) return;
    int src = __ldg(&ei[e]);
    int dst = __ldg(&ei[N_EDGES + e]);
    int p = atomicAdd(&g_cursor[src], 1);
    g_e2[p] = make_int2(src, dst);
}

// ---------------------------------------------------------------------------
// 4) edge scatter over SRC-SORTED edges — exact R7 winning shape (fixed
//    unroll, fire-and-forget vector REDs). Gather uses L1-allocating __ldg:
//    consecutive edges share src, so ~30/32 gathers are L1 hits -> external
//    gather traffic drops from 512B/edge to ~32B/edge.
// ---------------------------------------------------------------------------
__global__ void __launch_bounds__(256) k_edges(const float* __restrict__ x) {
    int warp = (blockIdx.x * blockDim.x + threadIdx.x) >> 5;
    int lane = threadIdx.x & 31;
    long long base = (long long)warp * EPW;
    if (base >= N_EDGES) return;

    int2 e = g_e2[base + lane];        // coalesced 256B pair load
    int src = e.x, dst = e.y;

    const float4* x4 = reinterpret_cast<const float4*>(x);

    #pragma unroll
    for (int j = 0; j < EPW; j++) {
        int s = __shfl_sync(0xffffffffu, src, j);
        int d = __shfl_sync(0xffffffffu, dst, j);
        float4 v = __ldg(&x4[(size_t)s * 32 + lane]);   // L1 hit for repeated src
        float* p = g_agg + (size_t)d * D + lane * 4;
        asm volatile("red.global.add.v4.f32 [%0], {%1, %2, %3, %4};"
                     :: "l"(p), "f"(v.x), "f"(v.y), "f"(v.z), "f"(v.w)
                     : "memory");
    }
}

// ---------------------------------------------------------------------------
// 5) epilogue: out = relu(scale*x + agg), re-zero agg, per-batch pooled sums
//    with run-length compression (batch sorted). One warp per 16 rows.
// ---------------------------------------------------------------------------
#define EPI_ROWS 16

__global__ void __launch_bounds__(256) k_epilogue(const float* __restrict__ x,
                                                  const float* __restrict__ eps,
                                                  const int* __restrict__ batch,
                                                  float* __restrict__ out) {
    int warp = (blockIdx.x * blockDim.x + threadIdx.x) >> 5;
    int lane = threadIdx.x & 31;
    int r0 = warp * EPI_ROWS;
    if (r0 >= N_NODES) return;
    int r1 = r0 + EPI_ROWS; if (r1 > N_NODES) r1 = N_NODES;

    float scale = 1.0f + eps[0];
    float4* agg4 = reinterpret_cast<float4*>(g_agg);
    const float4* x4 = reinterpret_cast<const float4*>(x);
    float4* out4 = reinterpret_cast<float4*>(out);
    const float4 zero4 = make_float4(0.f, 0.f, 0.f, 0.f);

    float4 acc = zero4;
    int cnt = 0;
    int cur = batch[r0];

    for (int r = r0; r < r1; r++) {
        size_t idx = (size_t)r * 32 + lane;
        float4 a  = __ldcg(&agg4[idx]);
        float4 xv = x4[idx];
        float4 v;
        v.x = fmaxf(fmaf(xv.x, scale, a.x), 0.f);
        v.y = fmaxf(fmaf(xv.y, scale, a.y), 0.f);
        v.z = fmaxf(fmaf(xv.z, scale, a.z), 0.f);
        v.w = fmaxf(fmaf(xv.w, scale, a.w), 0.f);
        out4[idx] = v;
        agg4[idx] = zero4;                 // self-restore for next replay

        int b = batch[r];
        if (b != cur) {
            float* p = &g_S[cur * D + lane * 4];
            asm volatile("red.global.add.v4.f32 [%0], {%1, %2, %3, %4};"
                         :: "l"(p), "f"(acc.x), "f"(acc.y), "f"(acc.z), "f"(acc.w)
                         : "memory");
            if (lane == 0) atomicAdd(&g_cnt[cur], (float)cnt);
            cur = b; acc = zero4; cnt = 0;
        }
        acc.x += v.x; acc.y += v.y; acc.z += v.z; acc.w += v.w;
        cnt++;
    }
    {
        float* p = &g_S[cur * D + lane * 4];
        asm volatile("red.global.add.v4.f32 [%0], {%1, %2, %3, %4};"
                     :: "l"(p), "f"(acc.x), "f"(acc.y), "f"(acc.z), "f"(acc.w)
                     : "memory");
        if (lane == 0) atomicAdd(&g_cnt[cur], (float)cnt);
    }
}

// ---------------------------------------------------------------------------
// 6) pooled2[b] = S[b] @ W + cnt[b]*bias. Reads then re-zeroes g_S / g_cnt.
// ---------------------------------------------------------------------------
__global__ void k_pool(const float* __restrict__ W,
                       const float* __restrict__ bias,
                       float* __restrict__ out2) {
    int b = blockIdx.x;     // 0..63
    int j = threadIdx.x;    // 0..127
    __shared__ float s[D];
    __shared__ float cntf;
    s[j] = g_S[b * D + j];
    g_S[b * D + j] = 0.0f;                 // self-restore
    if (j == 0) { cntf = g_cnt[b]; g_cnt[b] = 0.0f; }
    __syncthreads();

    float a0 = 0.f, a1 = 0.f, a2 = 0.f, a3 = 0.f;
    #pragma unroll
    for (int k = 0; k < D; k += 4) {
        a0 = fmaf(s[k + 0], __ldg(&W[(k + 0) * D + j]), a0);
        a1 = fmaf(s[k + 1], __ldg(&W[(k + 1) * D + j]), a1);
        a2 = fmaf(s[k + 2], __ldg(&W[(k + 2) * D + j]), a2);
        a3 = fmaf(s[k + 3], __ldg(&W[(k + 3) * D + j]), a3);
    }
    out2[b * D + j] = cntf * bias[j] + ((a0 + a1) + (a2 + a3));
}

// ---------------------------------------------------------------------------
// launch: x, eps, W_pred, b_pred, edge_index, batch -> out | pooled2
// ---------------------------------------------------------------------------
extern "C" void kernel_launch(void* const* d_in, const int* in_sizes, int n_in,
                              void* d_out, int out_size) {
    const float* x     = (const float*)d_in[0];
    const float* eps   = (const float*)d_in[1];
    const float* Wp    = (const float*)d_in[2];
    const float* bp    = (const float*)d_in[3];
    const int*   ei    = (const int*)d_in[4];
    const int*   batch = (const int*)d_in[5];

    float* out  = (float*)d_out;
    float* out2 = out + (size_t)N_NODES * D;

    k_setup<<<(N_NODES + 255) / 256, 256>>>();
    k_hist <<<(N_EDGES + 255) / 256, 256>>>(ei);
    k_scan <<<1, 1024>>>();
    k_fill <<<(N_EDGES + 255) / 256, 256>>>(ei);

    {
        int warps = (N_EDGES + EPW - 1) / EPW;               // 25000
        int blocks = (warps * 32 + 255) / 256;               // 3125
        k_edges<<<blocks, 256>>>(x);
    }

    {
        int warps = (N_NODES + EPI_ROWS - 1) / EPI_ROWS;     // 3125
        int blocks = (warps * 32 + 255) / 256;               // 391
        k_epilogue<<<blocks, 256>>>(x, eps, batch, out);
    }

    k_pool<<<NBATCH, 128>>>(Wp, bp, out2);
}